// round 10
// baseline (speedup 1.0000x reference)
#include <cuda_runtime.h>
#include <cstdint>

// Problem constants (fixed by setup_inputs: N=4, M=8192, D=64, k=16)
#define M_PTS   8192
#define D_DIM   64
#define K_NN    16
#define TILE_C  64         // candidates per shared tile (16 KB)
#define BLOCK_T 32         // 1 warp per block
#define QT      2          // queries per thread
#define QPB     (BLOCK_T * QT)        // 64 queries per block
#define N_BATCH 4
#define SPLIT   4          // candidate-dimension split
#define RANGE   (M_PTS / SPLIT)       // 2048 candidates per block
#define TOTAL_PTS (N_BATCH * M_PTS)   // 32768
#define NMK     (TOTAL_PTS * K_NN)    // 524288 edges per output array

typedef unsigned long long u64;

// Scratch (allocation-free rule: __device__ globals)
__device__ float g_sqnorm[TOTAL_PTS];
__device__ float g_pd[SPLIT * NMK];   // partial top-k distances
__device__ int   g_pi[SPLIT * NMK];   // partial top-k global ids

// ---------------------------------------------------------------------------
// Packed fp32x2 helpers (sm_103a FFMA2 — only reachable via PTX)
// ---------------------------------------------------------------------------
__device__ __forceinline__ u64 fma2(u64 a, u64 b, u64 c) {
    u64 d;
    asm("fma.rn.f32x2 %0, %1, %2, %3;" : "=l"(d) : "l"(a), "l"(b), "l"(c));
    return d;
}
// ((a.lo+a.hi) + (b.lo+b.hi)) — same association as rounds 8/9
__device__ __forceinline__ float hsum2x2(u64 a, u64 b) {
    float a0, a1, b0, b1;
    asm("mov.b64 {%0,%1}, %2;" : "=f"(a0), "=f"(a1) : "l"(a));
    asm("mov.b64 {%0,%1}, %2;" : "=f"(b0), "=f"(b1) : "l"(b));
    return (a0 + a1) + (b0 + b1);
}

// sorted-insert into register-resident top-k (strict <, ascending index order)
__device__ __forceinline__ void topk_insert(float (&bd)[K_NN], int (&bi)[K_NN],
                                            float d, int idx) {
    if (d < bd[K_NN - 1]) {
        bd[K_NN - 1] = d; bi[K_NN - 1] = idx;
#pragma unroll
        for (int j = K_NN - 1; j > 0; --j) {
            if (bd[j] < bd[j - 1]) {
                float td = bd[j]; bd[j] = bd[j - 1]; bd[j - 1] = td;
                int   ti = bi[j]; bi[j] = bi[j - 1]; bi[j - 1] = ti;
            }
        }
    }
}

// ---------------------------------------------------------------------------
// Kernel 1: squared norms per point
// ---------------------------------------------------------------------------
__global__ void sqnorm_kernel(const float* __restrict__ x) {
    int i = blockIdx.x * blockDim.x + threadIdx.x;
    if (i >= TOTAL_PTS) return;
    const float4* xv = reinterpret_cast<const float4*>(x + (size_t)i * D_DIM);
    float s = 0.f;
#pragma unroll
    for (int j = 0; j < D_DIM / 4; ++j) {
        float4 v = xv[j];
        s += v.x * v.x + v.y * v.y + v.z * v.z + v.w * v.w;
    }
    g_sqnorm[i] = s;
}

// ---------------------------------------------------------------------------
// Kernel 2: split-K KNN, 2 queries per thread (both register-resident).
// Each broadcast candidate LDS.128 now feeds 4 FFMA2 (2 queries x 2 lanes)
// -> shared-memory traffic per FMA halved vs rounds 6-9.
// ---------------------------------------------------------------------------
__global__ __launch_bounds__(BLOCK_T, 8)
void knn_kernel(const float* __restrict__ x) {
    __shared__ float4 s_c4[TILE_C * D_DIM / 4];  // 16 KB candidate tile
    __shared__ float  s_cx2[TILE_C];

    const int tid   = threadIdx.x;                 // 0..31
    const int qbase = blockIdx.x * QPB;            // 64 queries, same batch
    const int sp    = blockIdx.y;
    const int q0    = qbase + tid;
    const int q1    = q0 + BLOCK_T;
    const int n     = qbase >> 13;                 // / M_PTS (QPB | M_PTS)
    const int c_base = sp * RANGE;
    const float* xb = x + (size_t)n * M_PTS * D_DIM;

    // two query vectors as packed f32x2 registers (rows 256B-aligned)
    u64 qa[D_DIM / 2], qb[D_DIM / 2];
    {
        const ulonglong2* pa = reinterpret_cast<const ulonglong2*>(
            xb + (size_t)(q0 & (M_PTS - 1)) * D_DIM);
        const ulonglong2* pb = reinterpret_cast<const ulonglong2*>(
            xb + (size_t)(q1 & (M_PTS - 1)) * D_DIM);
#pragma unroll
        for (int j = 0; j < D_DIM / 4; ++j) {
            ulonglong2 ta = pa[j], tb = pb[j];
            qa[2 * j] = ta.x; qa[2 * j + 1] = ta.y;
            qb[2 * j] = tb.x; qb[2 * j + 1] = tb.y;
        }
    }
    const float qx2a = g_sqnorm[q0];
    const float qx2b = g_sqnorm[q1];

    float bda[K_NN], bdb[K_NN];
    int   bia[K_NN], bib[K_NN];
#pragma unroll
    for (int j = 0; j < K_NN; ++j) {
        bda[j] = __int_as_float(0x7f800000); bia[j] = 0;
        bdb[j] = __int_as_float(0x7f800000); bib[j] = 0;
    }

    for (int t0 = 0; t0 < RANGE; t0 += TILE_C) {
        __syncthreads();
        {
            const float4* g4 = reinterpret_cast<const float4*>(
                xb + (size_t)(c_base + t0) * D_DIM);
#pragma unroll
            for (int j = 0; j < (TILE_C * D_DIM / 4) / BLOCK_T; ++j)
                s_c4[tid + j * BLOCK_T] = g4[tid + j * BLOCK_T];
            s_cx2[tid]      = g_sqnorm[n * M_PTS + c_base + t0 + tid];
            s_cx2[tid + 32] = g_sqnorm[n * M_PTS + c_base + t0 + tid + 32];
        }
        __syncthreads();
        const ulonglong2* sc = reinterpret_cast<const ulonglong2*>(s_c4);

#pragma unroll 1
        for (int c = 0; c < TILE_C; c += 2) {
            // acc[query][cand] split over 2 packed k-lanes: 8 u64
            u64 a00_0 = 0, a00_1 = 0, a01_0 = 0, a01_1 = 0;
            u64 a10_0 = 0, a10_1 = 0, a11_0 = 0, a11_1 = 0;
#pragma unroll
            for (int j = 0; j < D_DIM / 4; ++j) {
                ulonglong2 u = sc[(c + 0) * (D_DIM / 4) + j];  // cand c
                ulonglong2 v = sc[(c + 1) * (D_DIM / 4) + j];  // cand c+1
                const u64 ka = qa[2 * j], kb = qa[2 * j + 1];
                const u64 kc = qb[2 * j], kd = qb[2 * j + 1];
                a00_0 = fma2(ka, u.x, a00_0);
                a00_1 = fma2(kb, u.y, a00_1);
                a01_0 = fma2(ka, v.x, a01_0);
                a01_1 = fma2(kb, v.y, a01_1);
                a10_0 = fma2(kc, u.x, a10_0);
                a10_1 = fma2(kd, u.y, a10_1);
                a11_0 = fma2(kc, v.x, a11_0);
                a11_1 = fma2(kd, v.y, a11_1);
            }
            const float cx0 = s_cx2[c], cx1 = s_cx2[c + 1];
            float d00 = fmaf(-2.f, hsum2x2(a00_0, a00_1), qx2a + cx0);
            float d01 = fmaf(-2.f, hsum2x2(a01_0, a01_1), qx2a + cx1);
            float d10 = fmaf(-2.f, hsum2x2(a10_0, a10_1), qx2b + cx0);
            float d11 = fmaf(-2.f, hsum2x2(a11_0, a11_1), qx2b + cx1);
            const int ci = c_base + t0 + c;

            if (fminf(d00, d01) < bda[K_NN - 1]) {
                topk_insert(bda, bia, d00, ci);
                topk_insert(bda, bia, d01, ci + 1);
            }
            if (fminf(d10, d11) < bdb[K_NN - 1]) {
                topk_insert(bdb, bib, d10, ci);
                topk_insert(bdb, bib, d11, ci + 1);
            }
        }
    }

    // write partial top-k (ids globalized across batches)
    const int off = n * M_PTS;
    const int pb0 = (sp * TOTAL_PTS + q0) * K_NN;
    const int pb1 = (sp * TOTAL_PTS + q1) * K_NN;
#pragma unroll
    for (int j = 0; j < K_NN; ++j) {
        g_pd[pb0 + j] = bda[j];
        g_pi[pb0 + j] = bia[j] + off;
        g_pd[pb1 + j] = bdb[j];
        g_pi[pb1 + j] = bib[j] + off;
    }
}

// ---------------------------------------------------------------------------
// Kernel 3: 4-way sorted merge of partial top-16 lists -> final edges (float)
// Tie-break: equal distance -> lower global index (matches jax top_k).
// ---------------------------------------------------------------------------
__global__ void merge_kernel(float* __restrict__ out_src,
                             float* __restrict__ out_dst) {
    int q = blockIdx.x * blockDim.x + threadIdx.x;
    if (q >= TOTAL_PTS) return;
    int p[SPLIT];
#pragma unroll
    for (int s = 0; s < SPLIT; ++s) p[s] = 0;

    const float fq = (float)q;
#pragma unroll 1
    for (int j = 0; j < K_NN; ++j) {
        float best  = __int_as_float(0x7f800000);
        int   besti = 0x7fffffff;
        int   bs    = 0;
#pragma unroll
        for (int s = 0; s < SPLIT; ++s) {
            if (p[s] < K_NN) {
                int o = (s * TOTAL_PTS + q) * K_NN + p[s];
                float dd = g_pd[o];
                int   ii = g_pi[o];
                if (dd < best || (dd == best && ii < besti)) {
                    best = dd; besti = ii; bs = s;
                }
            }
        }
        p[bs]++;
        out_src[q * K_NN + j] = (float)besti;
        out_dst[q * K_NN + j] = fq;
    }
}

// ---------------------------------------------------------------------------
// Launch
// ---------------------------------------------------------------------------
extern "C" void kernel_launch(void* const* d_in, const int* in_sizes, int n_in,
                              void* d_out, int out_size) {
    // x is the largest input (N*M*D floats); scalar k may precede or follow.
    int xi = 0;
    for (int i = 1; i < n_in; ++i)
        if (in_sizes[i] > in_sizes[xi]) xi = i;
    const float* x = (const float*)d_in[xi];

    float* out = (float*)d_out;

    sqnorm_kernel<<<(TOTAL_PTS + 255) / 256, 256>>>(x);
    dim3 grid(TOTAL_PTS / QPB, SPLIT);
    knn_kernel<<<grid, BLOCK_T>>>(x);
    merge_kernel<<<(TOTAL_PTS + 255) / 256, 256>>>(out, out + NMK);
}